// round 5
// baseline (speedup 1.0000x reference)
#include <cuda_runtime.h>

// Problem constants
#define BB   8
#define SQL  1024
#define DMOD 1024
#define NH   16
#define HD   64
#define ROWS (BB*SQL)   // 8192

// Scratch (device globals; no allocation allowed)
__device__ float g_xn [ROWS * DMOD];    // LayerNorm(x)  [8192,1024]
__device__ float g_q  [ROWS * DMOD];    // Q projection  [8192,1024]  (col = h*64+d)
__device__ float g_kv [ROWS * 2048];    // KV projection [8192,2048]  (K cols 0..1023, V cols 1024..2047)
__device__ float g_att[ROWS * DMOD];    // attention out [8192,1024]

typedef unsigned long long ull;

// ---- packed f32x2 helpers (Blackwell FFMA2) ----
__device__ __forceinline__ ull pk2(float x) {
    ull r; asm("mov.b64 %0, {%1, %1};" : "=l"(r) : "f"(x)); return r;
}
__device__ __forceinline__ void fma2(ull &d, ull a, ull b) {
    asm("fma.rn.f32x2 %0, %1, %2, %0;" : "+l"(d) : "l"(a), "l"(b));
}
__device__ __forceinline__ float2 up2(ull v) {
    float2 r; asm("mov.b64 {%0, %1}, %2;" : "=f"(r.x), "=f"(r.y) : "l"(v)); return r;
}

// ============================================================
// LayerNorm: one block per row (1024 elems), 256 threads
// ============================================================
__global__ void ln_kernel(const float* __restrict__ x,
                          const float* __restrict__ gam,
                          const float* __restrict__ bet)
{
    int row = blockIdx.x, tid = threadIdx.x;
    const float4* xr = (const float4*)(x + (size_t)row * DMOD);
    float4 v = xr[tid];
    float s  = v.x + v.y + v.z + v.w;
    float ss = v.x*v.x + v.y*v.y + v.z*v.z + v.w*v.w;
    #pragma unroll
    for (int o = 16; o > 0; o >>= 1) {
        s  += __shfl_down_sync(0xffffffffu, s,  o);
        ss += __shfl_down_sync(0xffffffffu, ss, o);
    }
    __shared__ float sh[2][8];
    __shared__ float res[2];
    int wid = tid >> 5, lane = tid & 31;
    if (lane == 0) { sh[0][wid] = s; sh[1][wid] = ss; }
    __syncthreads();
    if (tid == 0) {
        float a = 0.f, b = 0.f;
        #pragma unroll
        for (int i = 0; i < 8; i++) { a += sh[0][i]; b += sh[1][i]; }
        float mean = a * (1.f / 1024.f);
        float var  = b * (1.f / 1024.f) - mean * mean;
        res[0] = mean;
        res[1] = rsqrtf(var + 1e-3f);
    }
    __syncthreads();
    float mean = res[0], rstd = res[1];
    float4 g4 = ((const float4*)gam)[tid];
    float4 b4 = ((const float4*)bet)[tid];
    float4 o;
    o.x = (v.x - mean) * rstd * g4.x + b4.x;
    o.y = (v.y - mean) * rstd * g4.y + b4.y;
    o.z = (v.z - mean) * rstd * g4.z + b4.z;
    o.w = (v.w - mean) * rstd * g4.w + b4.w;
    ((float4*)(g_xn + (size_t)row * DMOD))[tid] = o;
}

// ============================================================
// SGEMM 128x128x8 with packed f32x2 accumulators.
// MODE 0: g_xn @ Wq  -> g_q        (+bias)
// MODE 1: g_xn @ Wkv -> g_kv       (+bias)
// MODE 2: g_att @ Wo -> Cout       (+bias + residual g_xn)
// M = 8192 always (grid.y = 64). All dims multiples of 128.
// ============================================================
template<int MODE>
__global__ __launch_bounds__(256, 2)
void sgemm_kernel(const float* __restrict__ Bm,
                  const float* __restrict__ bias,
                  float* __restrict__ Cout,
                  int N, int K)
{
    const float* A = (MODE == 2) ? g_att : g_xn;
    float* C = (MODE == 0) ? g_q : (MODE == 1) ? g_kv : Cout;

    __shared__ __align__(16) ull   As2[8][128];  // A value duplicated into both f32 lanes
    __shared__ __align__(16) float Bs [8][128];

    int tid = threadIdx.x;
    int tx = tid & 15, ty = tid >> 4;
    int ar = tid >> 1, ac = (tid & 1) * 4;   // A tile load: 128 rows x 8 k
    int br = tid >> 5, bc = (tid & 31) * 4;  // B tile load: 8 k x 128 cols

    const float* Ap = A  + (size_t)(blockIdx.y * 128) * K;
    const float* Bp = Bm + blockIdx.x * 128;

    ull acc[8][4];
    #pragma unroll
    for (int i = 0; i < 8; i++)
        #pragma unroll
        for (int j = 0; j < 4; j++) acc[i][j] = 0ULL;

    for (int k0 = 0; k0 < K; k0 += 8) {
        float4 ga = *(const float4*)&Ap[ar * K + k0 + ac];
        float4 gb = *(const float4*)&Bp[(k0 + br) * N + bc];
        __syncthreads();
        As2[ac + 0][ar] = pk2(ga.x);
        As2[ac + 1][ar] = pk2(ga.y);
        As2[ac + 2][ar] = pk2(ga.z);
        As2[ac + 3][ar] = pk2(ga.w);
        *(float4*)&Bs[br][bc] = gb;
        __syncthreads();
        #pragma unroll
        for (int kk = 0; kk < 8; kk++) {
            ulonglong2 a01 = *(ulonglong2*)&As2[kk][ty * 4];
            ulonglong2 a23 = *(ulonglong2*)&As2[kk][ty * 4 + 2];
            ulonglong2 a45 = *(ulonglong2*)&As2[kk][64 + ty * 4];
            ulonglong2 a67 = *(ulonglong2*)&As2[kk][64 + ty * 4 + 2];
            ulonglong2 b01 = *(ulonglong2*)&Bs[kk][tx * 4];
            ulonglong2 b23 = *(ulonglong2*)&Bs[kk][64 + tx * 4];
            ull av[8] = {a01.x, a01.y, a23.x, a23.y, a45.x, a45.y, a67.x, a67.y};
            ull bv[4] = {b01.x, b01.y, b23.x, b23.y};
            #pragma unroll
            for (int i = 0; i < 8; i++) {
                fma2(acc[i][0], av[i], bv[0]);
                fma2(acc[i][1], av[i], bv[1]);
                fma2(acc[i][2], av[i], bv[2]);
                fma2(acc[i][3], av[i], bv[3]);
            }
        }
    }

    #pragma unroll
    for (int i = 0; i < 8; i++) {
        int rl   = (i < 4) ? ty * 4 + i : 64 + ty * 4 + (i - 4);
        int grow = blockIdx.y * 128 + rl;
        #pragma unroll
        for (int j = 0; j < 4; j++) {
            int cl   = (j < 2) ? tx * 4 + j * 2 : 64 + tx * 4 + (j - 2) * 2;
            int gcol = blockIdx.x * 128 + cl;
            float2 v = up2(acc[i][j]);
            v.x += bias[gcol];
            v.y += bias[gcol + 1];
            if (MODE == 2) {
                v.x += g_xn[(size_t)grow * DMOD + gcol];
                v.y += g_xn[(size_t)grow * DMOD + gcol + 1];
            }
            *(float2*)&C[(size_t)grow * N + gcol] = v;
        }
    }
}

// ============================================================
// Attention: one thread per query row (fully private softmax).
// Block: 128 q rows, grid (SQ/128=8, H=16, B=8). KV tiles of 32.
// Causal (self-attn) + key-padding mask.
// ============================================================
__global__ __launch_bounds__(128, 2)
void attn_kernel(const int* __restrict__ lens)
{
    __shared__ __align__(16) float4 Ks[32][16];
    __shared__ __align__(16) float4 Vs[32][16];

    int tid = threadIdx.x;
    int b = blockIdx.z, h = blockIdx.y;
    int qb = blockIdx.x * 128;
    int q  = qb + tid;
    int len = lens[b];

    const float* qp = g_q + ((size_t)(b * SQL + q) * DMOD + h * 64);
    float4 qv[16];
    #pragma unroll
    for (int i = 0; i < 16; i++) qv[i] = ((const float4*)qp)[i];

    float4 ov[16];
    #pragma unroll
    for (int i = 0; i < 16; i++) ov[i] = make_float4(0.f, 0.f, 0.f, 0.f);
    float m = -1e30f, l = 0.f;

    int kend = min(len, qb + 128);   // causal upper bound for this block + length mask
    for (int t0 = 0; t0 < kend; t0 += 32) {
        __syncthreads();
        #pragma unroll
        for (int i = 0; i < 4; i++) {
            int p = tid + 128 * i;
            int r = p >> 4, c = p & 15;
            size_t base = (size_t)(b * SQL + t0 + r) * 2048 + h * 64 + c * 4;
            Ks[r][c] = *(const float4*)&g_kv[base];
            Vs[r][c] = *(const float4*)&g_kv[base + 1024];
        }
        __syncthreads();

        if (t0 <= q) {
            float s[32];
            float tm = -1e30f;
            #pragma unroll
            for (int j = 0; j < 32; j++) {
                int kv = t0 + j;
                float sc = -1e30f;
                if (kv <= q && kv < len) {
                    float a = 0.f;
                    #pragma unroll
                    for (int d = 0; d < 16; d++) {
                        float4 kk = Ks[j][d];
                        a += qv[d].x * kk.x + qv[d].y * kk.y
                           + qv[d].z * kk.z + qv[d].w * kk.w;
                    }
                    sc = a * 0.125f;   // 1/sqrt(64)
                }
                s[j] = sc;
                tm = fmaxf(tm, sc);
            }
            float nm   = fmaxf(m, tm);
            float corr = __expf(m - nm);
            l *= corr;
            #pragma unroll
            for (int i = 0; i < 16; i++) {
                ov[i].x *= corr; ov[i].y *= corr; ov[i].z *= corr; ov[i].w *= corr;
            }
            m = nm;
            #pragma unroll
            for (int j = 0; j < 32; j++) {
                float p = __expf(s[j] - m);  // masked -> 0
                l += p;
                #pragma unroll
                for (int d = 0; d < 16; d++) {
                    float4 vv = Vs[j][d];
                    ov[d].x += p * vv.x; ov[d].y += p * vv.y;
                    ov[d].z += p * vv.z; ov[d].w += p * vv.w;
                }
            }
        }
    }

    float rl = 1.f / l;   // row always has at least key 0 valid
    float* op = g_att + ((size_t)(b * SQL + q) * DMOD + h * 64);
    #pragma unroll
    for (int i = 0; i < 16; i++) {
        float4 w;
        w.x = ov[i].x * rl; w.y = ov[i].y * rl;
        w.z = ov[i].z * rl; w.w = ov[i].w * rl;
        ((float4*)op)[i] = w;
    }
}

// ============================================================
// Launch
// ============================================================
extern "C" void kernel_launch(void* const* d_in, const int* in_sizes, int n_in,
                              void* d_out, int out_size)
{
    const float* x    = (const float*)d_in[0];
    // d_in[1] == key_value_sequences, identical to x (self-attention path)
    const int*   lens = (const int*)  d_in[2];
    const float* Wq   = (const float*)d_in[3];
    const float* bq   = (const float*)d_in[4];
    const float* Wkv  = (const float*)d_in[5];
    const float* bkv  = (const float*)d_in[6];
    const float* Wo   = (const float*)d_in[7];
    const float* bo   = (const float*)d_in[8];
    const float* gam  = (const float*)d_in[9];
    const float* bet  = (const float*)d_in[10];
    float* out = (float*)d_out;

    // 1. LayerNorm (shared by q path and kv path: self-attention)
    ln_kernel<<<ROWS, 256>>>(x, gam, bet);
    // 2. Q = xn @ Wq + bq          [8192,1024]
    sgemm_kernel<0><<<dim3(8, 64), 256>>>(Wq, bq, nullptr, 1024, 1024);
    // 3. KV = xn @ Wkv + bkv       [8192,2048]
    sgemm_kernel<1><<<dim3(16, 64), 256>>>(Wkv, bkv, nullptr, 2048, 1024);
    // 4. attention (causal + padding), per-head flash
    attn_kernel<<<dim3(8, 16, 8), 128>>>(lens);
    // 5. out = att @ Wo + bo + residual(xn)
    sgemm_kernel<2><<<dim3(8, 64), 256>>>(Wo, bo, out, 1024, 1024);
}

// round 7
// speedup vs baseline: 3.0345x; 3.0345x over previous
#include <cuda_runtime.h>
#include <cstdint>

typedef unsigned long long ull;

// Problem constants
#define BB   8
#define SQL  1024
#define DMOD 1024
#define ROWS (BB*SQL)   // 8192

// Scratch (device globals; no allocation allowed)
__device__ float g_xn  [ROWS * DMOD];    // LayerNorm(x) fp32 (also residual)
__device__ float g_q   [ROWS * DMOD];    // Q projection
__device__ float g_kv  [ROWS * 2048];    // K cols 0..1023, V cols 1024..2047
__device__ float g_att [ROWS * DMOD];    // attention out
__device__ float g_wqt [1024 * 1024];    // Wq^T  [N,K] tf32-rounded
__device__ float g_wkvt[2048 * 1024];    // Wkv^T [N,K] tf32-rounded
__device__ float g_wot [1024 * 1024];    // Wo^T  [N,K] tf32-rounded

// ---------------- helpers ----------------
__device__ __forceinline__ ull pk2(float x) {
    ull r; asm("mov.b64 %0, {%1, %1};" : "=l"(r) : "f"(x)); return r;
}
__device__ __forceinline__ void fma2(ull &d, ull a, ull b) {
    asm("fma.rn.f32x2 %0, %1, %2, %0;" : "+l"(d) : "l"(a), "l"(b));
}
__device__ __forceinline__ void mul2(ull &d, ull a, ull b) {
    asm("mul.rn.f32x2 %0, %1, %2;" : "=l"(d) : "l"(a), "l"(b));
}
__device__ __forceinline__ float2 up2(ull v) {
    float2 r; asm("mov.b64 {%0, %1}, %2;" : "=f"(r.x), "=f"(r.y) : "l"(v)); return r;
}
__device__ __forceinline__ float tf32r(float x) {
    uint32_t u; asm("cvt.rna.tf32.f32 %0, %1;" : "=r"(u) : "f"(x));
    return __uint_as_float(u);
}
// mma.sync m16n8k8 tf32 (sm_80+ PTX; compiles to HMMA on base sm_103 target)
__device__ __forceinline__ void mma1688(float* c, const uint32_t* a, const uint32_t* b) {
    asm volatile(
        "mma.sync.aligned.m16n8k8.row.col.f32.tf32.tf32.f32 "
        "{%0,%1,%2,%3}, {%4,%5,%6,%7}, {%8,%9}, {%0,%1,%2,%3};"
        : "+f"(c[0]), "+f"(c[1]), "+f"(c[2]), "+f"(c[3])
        : "r"(a[0]), "r"(a[1]), "r"(a[2]), "r"(a[3]), "r"(b[0]), "r"(b[1]));
}

// ============================================================
// LayerNorm: one block per row (1024 elems), 256 threads
// ============================================================
__global__ void ln_kernel(const float* __restrict__ x,
                          const float* __restrict__ gam,
                          const float* __restrict__ bet)
{
    int row = blockIdx.x, tid = threadIdx.x;
    const float4* xr = (const float4*)(x + (size_t)row * DMOD);
    float4 v = xr[tid];
    float s  = v.x + v.y + v.z + v.w;
    float ss = v.x*v.x + v.y*v.y + v.z*v.z + v.w*v.w;
    #pragma unroll
    for (int o = 16; o > 0; o >>= 1) {
        s  += __shfl_down_sync(0xffffffffu, s,  o);
        ss += __shfl_down_sync(0xffffffffu, ss, o);
    }
    __shared__ float sh[2][8];
    __shared__ float res[2];
    int wid = tid >> 5, lane = tid & 31;
    if (lane == 0) { sh[0][wid] = s; sh[1][wid] = ss; }
    __syncthreads();
    if (tid == 0) {
        float a = 0.f, b = 0.f;
        #pragma unroll
        for (int i = 0; i < 8; i++) { a += sh[0][i]; b += sh[1][i]; }
        float mean = a * (1.f / 1024.f);
        float var  = b * (1.f / 1024.f) - mean * mean;
        res[0] = mean;
        res[1] = rsqrtf(var + 1e-3f);
    }
    __syncthreads();
    float mean = res[0], rstd = res[1];
    float4 g4 = ((const float4*)gam)[tid];
    float4 b4 = ((const float4*)bet)[tid];
    float4 o;
    o.x = (v.x - mean) * rstd * g4.x + b4.x;
    o.y = (v.y - mean) * rstd * g4.y + b4.y;
    o.z = (v.z - mean) * rstd * g4.z + b4.z;
    o.w = (v.w - mean) * rstd * g4.w + b4.w;
    ((float4*)(g_xn + (size_t)row * DMOD))[tid] = o;
}

// ============================================================
// Weight transpose + round-to-nearest tf32.
// W[K=1024, N] row-major  ->  WT[N, K=1024] row-major (K-major B for mma row.col)
// ============================================================
template<int W>
__global__ void transpose_rna(const float* __restrict__ Wm, int N)
{
    float* WT = (W == 0) ? g_wqt : (W == 1) ? g_wkvt : g_wot;
    __shared__ float t[32][33];
    int bn = blockIdx.x * 32, bk = blockIdx.y * 32;
    int x = threadIdx.x, y = threadIdx.y;
    #pragma unroll
    for (int i = 0; i < 4; i++)
        t[y + i*8][x] = Wm[(size_t)(bk + y + i*8) * N + bn + x];
    __syncthreads();
    #pragma unroll
    for (int i = 0; i < 4; i++)
        WT[(size_t)(bn + y + i*8) * 1024 + bk + x] = tf32r(t[x][y + i*8]);
}

// ============================================================
// tf32 mma.sync GEMM. CTA tile 128x128, K=1024 in chunks of 16,
// double-buffered smem, one __syncthreads per chunk.
// 8 warps in 2(M) x 4(N); warp tile 64x32 = 4 mfrag x 4 nfrag of m16n8k8.
// MODE 0: g_xn  @ Wq^T  -> g_q    (+bias)
// MODE 1: g_xn  @ Wkv^T -> g_kv   (+bias)
// MODE 2: g_att @ Wo^T  -> Cout   (+bias + residual g_xn)
// ============================================================
#define PAD 136   // word stride: k-rows land 8 banks apart -> conflict-free frags

template<int MODE>
__global__ __launch_bounds__(256, 2)
void mma_gemm(const float* __restrict__ bias, float* __restrict__ Cout, int N)
{
    const float* A  = (MODE == 2) ? g_att : g_xn;
    const float* Bt = (MODE == 0) ? g_wqt : (MODE == 1) ? g_wkvt : g_wot;
    float* C = (MODE == 0) ? g_q : (MODE == 1) ? g_kv : Cout;

    __shared__ float As[2][16][PAD];
    __shared__ float Bs[2][16][PAD];

    int tid = threadIdx.x;
    int wid = tid >> 5, lane = tid & 31;
    int warp_m = wid & 1, warp_n = wid >> 1;       // 2 x 4
    int r = lane >> 2, cq = lane & 3;

    // loader: thread covers row lr, cols lc..lc+7 of the 128x16 chunk
    int lr = tid >> 1;
    int lc = (tid & 1) * 8;
    const float* Ap = A  + (size_t)(blockIdx.y * 128 + lr) * 1024 + lc;
    const float* Bp = Bt + (size_t)(blockIdx.x * 128 + lr) * 1024 + lc;

    float acc[4][4][4];
    #pragma unroll
    for (int i = 0; i < 4; i++)
        #pragma unroll
        for (int j = 0; j < 4; j++)
            #pragma unroll
            for (int k = 0; k < 4; k++) acc[i][j][k] = 0.f;

    float4 pa0 = *(const float4*)(Ap);
    float4 pa1 = *(const float4*)(Ap + 4);
    float4 pb0 = *(const float4*)(Bp);
    float4 pb1 = *(const float4*)(Bp + 4);

    // stage store (tf32-rounded, transposed to [k][m])
    auto stg = [&](int s, float4 a0, float4 a1, float4 b0, float4 b1) {
        float* da = &As[s][lc][lr];
        da[0*PAD] = tf32r(a0.x); da[1*PAD] = tf32r(a0.y);
        da[2*PAD] = tf32r(a0.z); da[3*PAD] = tf32r(a0.w);
        da[4*PAD] = tf32r(a1.x); da[5*PAD] = tf32r(a1.y);
        da[6*PAD] = tf32r(a1.z); da[7*PAD] = tf32r(a1.w);
        float* db = &Bs[s][lc][lr];
        db[0*PAD] = tf32r(b0.x); db[1*PAD] = tf32r(b0.y);
        db[2*PAD] = tf32r(b0.z); db[3*PAD] = tf32r(b0.w);
        db[4*PAD] = tf32r(b1.x); db[5*PAD] = tf32r(b1.y);
        db[6*PAD] = tf32r(b1.z); db[7*PAD] = tf32r(b1.w);
    };

    stg(0, pa0, pa1, pb0, pb1);
    __syncthreads();

    const int NC = 64;   // 1024 / 16
    for (int c = 0; c < NC; c++) {
        int s = c & 1;
        if (c + 1 < NC) {
            const float* ap = Ap + (c + 1) * 16;
            const float* bp = Bp + (c + 1) * 16;
            pa0 = *(const float4*)(ap);
            pa1 = *(const float4*)(ap + 4);
            pb0 = *(const float4*)(bp);
            pb1 = *(const float4*)(bp + 4);
        }
        #pragma unroll
        for (int ks = 0; ks < 2; ks++) {
            int kb = ks * 8;
            uint32_t bf[4][2];
            #pragma unroll
            for (int nf = 0; nf < 4; nf++) {
                int col = warp_n * 32 + nf * 8 + r;
                bf[nf][0] = __float_as_uint(Bs[s][kb + cq][col]);
                bf[nf][1] = __float_as_uint(Bs[s][kb + cq + 4][col]);
            }
            #pragma unroll
            for (int mf = 0; mf < 4; mf++) {
                int row0 = warp_m * 64 + mf * 16 + r;
                uint32_t af[4];
                af[0] = __float_as_uint(As[s][kb + cq][row0]);
                af[1] = __float_as_uint(As[s][kb + cq][row0 + 8]);
                af[2] = __float_as_uint(As[s][kb + cq + 4][row0]);
                af[3] = __float_as_uint(As[s][kb + cq + 4][row0 + 8]);
                #pragma unroll
                for (int nf = 0; nf < 4; nf++)
                    mma1688(acc[mf][nf], af, bf[nf]);
            }
        }
        if (c + 1 < NC) {
            stg(s ^ 1, pa0, pa1, pb0, pb1);
            __syncthreads();
        }
    }

    // Epilogue: c0,c1 -> (row, col..col+1); c2,c3 -> (row+8, col..col+1)
    #pragma unroll
    for (int mf = 0; mf < 4; mf++) {
        int row0 = blockIdx.y * 128 + warp_m * 64 + mf * 16 + r;
        #pragma unroll
        for (int nf = 0; nf < 4; nf++) {
            int gcol = blockIdx.x * 128 + warp_n * 32 + nf * 8 + cq * 2;
            float2 bv = *(const float2*)(bias + gcol);
            float2 v0, v1;
            v0.x = acc[mf][nf][0] + bv.x;
            v0.y = acc[mf][nf][1] + bv.y;
            v1.x = acc[mf][nf][2] + bv.x;
            v1.y = acc[mf][nf][3] + bv.y;
            if (MODE == 2) {
                float2 r0 = *(const float2*)(g_xn + (size_t)row0 * 1024 + gcol);
                float2 r1 = *(const float2*)(g_xn + (size_t)(row0 + 8) * 1024 + gcol);
                v0.x += r0.x; v0.y += r0.y;
                v1.x += r1.x; v1.y += r1.y;
            }
            *(float2*)(C + (size_t)row0 * N + gcol)       = v0;
            *(float2*)(C + (size_t)(row0 + 8) * N + gcol) = v1;
        }
    }
}

// ============================================================
// Attention: one thread per query row, FFMA2-packed inner loops.
// Block: 128 q rows, grid (8, 16, 8). KV tiles of 32.
// ============================================================
__global__ __launch_bounds__(128, 2)
void attn_kernel(const int* __restrict__ lens)
{
    __shared__ __align__(16) float4 Ks[32][16];
    __shared__ __align__(16) float4 Vs[32][16];

    int tid = threadIdx.x;
    int b = blockIdx.z, h = blockIdx.y;
    int qb = blockIdx.x * 128;
    int q  = qb + tid;
    int len = lens[b];

    const ulonglong2* qpp = (const ulonglong2*)(g_q + ((size_t)(b * SQL + q) * DMOD + h * 64));
    ull qp[32];
    #pragma unroll
    for (int i = 0; i < 16; i++) { ulonglong2 u = qpp[i]; qp[2*i] = u.x; qp[2*i+1] = u.y; }

    ull ov[32];
    #pragma unroll
    for (int i = 0; i < 32; i++) ov[i] = 0ULL;
    float m = -1e30f, l = 0.f;

    int kend = min(len, qb + 128);   // causal + length bound for this block
    for (int t0 = 0; t0 < kend; t0 += 32) {
        __syncthreads();
        #pragma unroll
        for (int i = 0; i < 4; i++) {
            int p = tid + 128 * i;
            int rr = p >> 4, cc = p & 15;
            size_t base = (size_t)(b * SQL + t0 + rr) * 2048 + h * 64 + cc * 4;
            Ks[rr][cc] = *(const float4*)&g_kv[base];
            Vs[rr][cc] = *(const float4*)&g_kv[base + 1024];
        }
        __syncthreads();

        if (t0 <= q) {
            float s[32];
            float tm = -1e30f;
            #pragma unroll
            for (int j = 0; j < 32; j++) {
                int kv = t0 + j;
                float sc = -1e30f;
                if (kv <= q && kv < len) {
                    ull acc0 = 0ULL, acc1 = 0ULL;
                    const ulonglong2* kp = (const ulonglong2*)Ks[j];
                    #pragma unroll
                    for (int d = 0; d < 16; d++) {
                        ulonglong2 kk = kp[d];
                        fma2(acc0, qp[2*d],   kk.x);
                        fma2(acc1, qp[2*d+1], kk.y);
                    }
                    float2 h0 = up2(acc0), h1 = up2(acc1);
                    sc = (h0.x + h0.y + h1.x + h1.y) * 0.125f;   // 1/sqrt(64)
                }
                s[j] = sc;
                tm = fmaxf(tm, sc);
            }
            float nm   = fmaxf(m, tm);
            float corr = __expf(m - nm);
            l *= corr;
            ull pc = pk2(corr);
            #pragma unroll
            for (int i = 0; i < 32; i++) mul2(ov[i], ov[i], pc);
            m = nm;
            #pragma unroll
            for (int j = 0; j < 32; j++) {
                float p = __expf(s[j] - m);   // masked -> 0
                l += p;
                ull pp = pk2(p);
                const ulonglong2* vp = (const ulonglong2*)Vs[j];
                #pragma unroll
                for (int d = 0; d < 16; d++) {
                    ulonglong2 vv = vp[d];
                    fma2(ov[2*d],   pp, vv.x);
                    fma2(ov[2*d+1], pp, vv.y);
                }
            }
        }
    }

    float rl = 1.f / l;
    float* op = g_att + ((size_t)(b * SQL + q) * DMOD + h * 64);
    #pragma unroll
    for (int i = 0; i < 16; i++) {
        float2 lo = up2(ov[2*i]), hi = up2(ov[2*i+1]);
        ((float4*)op)[i] = make_float4(lo.x * rl, lo.y * rl, hi.x * rl, hi.y * rl);
    }
}

// ============================================================
// Launch
// ============================================================
extern "C" void kernel_launch(void* const* d_in, const int* in_sizes, int n_in,
                              void* d_out, int out_size)
{
    const float* x    = (const float*)d_in[0];
    // d_in[1] == key_value_sequences, identical to x (self-attention path)
    const int*   lens = (const int*)  d_in[2];
    const float* Wq   = (const float*)d_in[3];
    const float* bq   = (const float*)d_in[4];
    const float* Wkv  = (const float*)d_in[5];
    const float* bkv  = (const float*)d_in[6];
    const float* Wo   = (const float*)d_in[7];
    const float* bo   = (const float*)d_in[8];
    const float* gam  = (const float*)d_in[9];
    const float* bet  = (const float*)d_in[10];
    float* out = (float*)d_out;

    // 1. LayerNorm (shared by q and kv paths)
    ln_kernel<<<ROWS, 256>>>(x, gam, bet);
    // 2. transpose + tf32-round the weights
    transpose_rna<0><<<dim3(32, 32), dim3(32, 8)>>>(Wq, 1024);
    transpose_rna<1><<<dim3(64, 32), dim3(32, 8)>>>(Wkv, 2048);
    transpose_rna<2><<<dim3(32, 32), dim3(32, 8)>>>(Wo, 1024);
    // 3. projections on mma.sync tf32
    mma_gemm<0><<<dim3(8, 64),  256>>>(bq,  nullptr, 1024);
    mma_gemm<1><<<dim3(16, 64), 256>>>(bkv, nullptr, 2048);
    // 4. attention (causal + padding), per-head flash, FFMA2
    attn_kernel<<<dim3(8, 16, 8), 128>>>(lens);
    // 5. out = att @ Wo + bo + residual(xn)
    mma_gemm<2><<<dim3(8, 64),  256>>>(bo, out, 1024);
}

// round 8
// speedup vs baseline: 4.0367x; 1.3303x over previous
#include <cuda_runtime.h>
#include <cstdint>

typedef unsigned long long ull;

// Problem constants
#define BB   8
#define SQL  1024
#define DMOD 1024
#define ROWS (BB*SQL)   // 8192

// Scratch (device globals; no allocation allowed)
__device__ float g_xn  [ROWS * DMOD];    // LayerNorm(x) fp32 (also residual)
__device__ float g_q   [ROWS * DMOD];    // Q projection
__device__ float g_kv  [ROWS * 2048];    // K cols 0..1023, V cols 1024..2047
__device__ float g_att [ROWS * DMOD];    // attention out
__device__ float g_wqt [1024 * 1024];    // Wq^T  [N,K] tf32-rounded
__device__ float g_wkvt[2048 * 1024];    // Wkv^T [N,K] tf32-rounded
__device__ float g_wot [1024 * 1024];    // Wo^T  [N,K] tf32-rounded

// ---------------- helpers ----------------
__device__ __forceinline__ float tf32r(float x) {
    uint32_t u; asm("cvt.rna.tf32.f32 %0, %1;" : "=r"(u) : "f"(x));
    return __uint_as_float(u);
}
// mma.sync m16n8k8 tf32 (compiles to HMMA on base sm_103 target)
__device__ __forceinline__ void mma1688(float* c, const uint32_t* a, const uint32_t* b) {
    asm volatile(
        "mma.sync.aligned.m16n8k8.row.col.f32.tf32.tf32.f32 "
        "{%0,%1,%2,%3}, {%4,%5,%6,%7}, {%8,%9}, {%0,%1,%2,%3};"
        : "+f"(c[0]), "+f"(c[1]), "+f"(c[2]), "+f"(c[3])
        : "r"(a[0]), "r"(a[1]), "r"(a[2]), "r"(a[3]), "r"(b[0]), "r"(b[1]));
}

// ============================================================
// LayerNorm: one block per row (1024 elems), 256 threads
// ============================================================
__global__ void ln_kernel(const float* __restrict__ x,
                          const float* __restrict__ gam,
                          const float* __restrict__ bet)
{
    int row = blockIdx.x, tid = threadIdx.x;
    const float4* xr = (const float4*)(x + (size_t)row * DMOD);
    float4 v = xr[tid];
    float s  = v.x + v.y + v.z + v.w;
    float ss = v.x*v.x + v.y*v.y + v.z*v.z + v.w*v.w;
    #pragma unroll
    for (int o = 16; o > 0; o >>= 1) {
        s  += __shfl_down_sync(0xffffffffu, s,  o);
        ss += __shfl_down_sync(0xffffffffu, ss, o);
    }
    __shared__ float sh[2][8];
    __shared__ float res[2];
    int wid = tid >> 5, lane = tid & 31;
    if (lane == 0) { sh[0][wid] = s; sh[1][wid] = ss; }
    __syncthreads();
    if (tid == 0) {
        float a = 0.f, b = 0.f;
        #pragma unroll
        for (int i = 0; i < 8; i++) { a += sh[0][i]; b += sh[1][i]; }
        float mean = a * (1.f / 1024.f);
        float var  = b * (1.f / 1024.f) - mean * mean;
        res[0] = mean;
        res[1] = rsqrtf(var + 1e-3f);
    }
    __syncthreads();
    float mean = res[0], rstd = res[1];
    float4 g4 = ((const float4*)gam)[tid];
    float4 b4 = ((const float4*)bet)[tid];
    float4 o;
    o.x = (v.x - mean) * rstd * g4.x + b4.x;
    o.y = (v.y - mean) * rstd * g4.y + b4.y;
    o.z = (v.z - mean) * rstd * g4.z + b4.z;
    o.w = (v.w - mean) * rstd * g4.w + b4.w;
    ((float4*)(g_xn + (size_t)row * DMOD))[tid] = o;
}

// ============================================================
// Weight transpose + round-to-nearest tf32.
// W[K=1024, N] row-major  ->  WT[N, K=1024] row-major (K-major B for mma row.col)
// ============================================================
template<int W>
__global__ void transpose_rna(const float* __restrict__ Wm, int N)
{
    float* WT = (W == 0) ? g_wqt : (W == 1) ? g_wkvt : g_wot;
    __shared__ float t[32][33];
    int bn = blockIdx.x * 32, bk = blockIdx.y * 32;
    int x = threadIdx.x, y = threadIdx.y;
    #pragma unroll
    for (int i = 0; i < 4; i++)
        t[y + i*8][x] = Wm[(size_t)(bk + y + i*8) * N + bn + x];
    __syncthreads();
    #pragma unroll
    for (int i = 0; i < 4; i++)
        WT[(size_t)(bn + y + i*8) * 1024 + bk + x] = tf32r(t[x][y + i*8]);
}

// ============================================================
// tf32 mma.sync GEMM. CTA tile 128x128, K chunks of 16, double-buffered.
// 8 warps in 2(M) x 4(N); warp tile 64x32.
// MODE 0: g_xn  @ Wq^T  -> g_q    (+bias)
// MODE 1: g_xn  @ Wkv^T -> g_kv   (+bias)
// MODE 2: g_att @ Wo^T  -> Cout   (+bias + residual g_xn)
// ============================================================
#define PAD 136

template<int MODE>
__global__ __launch_bounds__(256, 2)
void mma_gemm(const float* __restrict__ bias, float* __restrict__ Cout, int N)
{
    const float* A  = (MODE == 2) ? g_att : g_xn;
    const float* Bt = (MODE == 0) ? g_wqt : (MODE == 1) ? g_wkvt : g_wot;
    float* C = (MODE == 0) ? g_q : (MODE == 1) ? g_kv : Cout;

    __shared__ float As[2][16][PAD];
    __shared__ float Bs[2][16][PAD];

    int tid = threadIdx.x;
    int wid = tid >> 5, lane = tid & 31;
    int warp_m = wid & 1, warp_n = wid >> 1;
    int r = lane >> 2, cq = lane & 3;

    int lr = tid >> 1;
    int lc = (tid & 1) * 8;
    const float* Ap = A  + (size_t)(blockIdx.y * 128 + lr) * 1024 + lc;
    const float* Bp = Bt + (size_t)(blockIdx.x * 128 + lr) * 1024 + lc;

    float acc[4][4][4];
    #pragma unroll
    for (int i = 0; i < 4; i++)
        #pragma unroll
        for (int j = 0; j < 4; j++)
            #pragma unroll
            for (int k = 0; k < 4; k++) acc[i][j][k] = 0.f;

    float4 pa0 = *(const float4*)(Ap);
    float4 pa1 = *(const float4*)(Ap + 4);
    float4 pb0 = *(const float4*)(Bp);
    float4 pb1 = *(const float4*)(Bp + 4);

    auto stg = [&](int s, float4 a0, float4 a1, float4 b0, float4 b1) {
        float* da = &As[s][lc][lr];
        da[0*PAD] = tf32r(a0.x); da[1*PAD] = tf32r(a0.y);
        da[2*PAD] = tf32r(a0.z); da[3*PAD] = tf32r(a0.w);
        da[4*PAD] = tf32r(a1.x); da[5*PAD] = tf32r(a1.y);
        da[6*PAD] = tf32r(a1.z); da[7*PAD] = tf32r(a1.w);
        float* db = &Bs[s][lc][lr];
        db[0*PAD] = tf32r(b0.x); db[1*PAD] = tf32r(b0.y);
        db[2*PAD] = tf32r(b0.z); db[3*PAD] = tf32r(b0.w);
        db[4*PAD] = tf32r(b1.x); db[5*PAD] = tf32r(b1.y);
        db[6*PAD] = tf32r(b1.z); db[7*PAD] = tf32r(b1.w);
    };

    stg(0, pa0, pa1, pb0, pb1);
    __syncthreads();

    const int NC = 64;
    for (int c = 0; c < NC; c++) {
        int s = c & 1;
        if (c + 1 < NC) {
            const float* ap = Ap + (c + 1) * 16;
            const float* bp = Bp + (c + 1) * 16;
            pa0 = *(const float4*)(ap);
            pa1 = *(const float4*)(ap + 4);
            pb0 = *(const float4*)(bp);
            pb1 = *(const float4*)(bp + 4);
        }
        #pragma unroll
        for (int ks = 0; ks < 2; ks++) {
            int kb = ks * 8;
            uint32_t bf[4][2];
            #pragma unroll
            for (int nf = 0; nf < 4; nf++) {
                int col = warp_n * 32 + nf * 8 + r;
                bf[nf][0] = __float_as_uint(Bs[s][kb + cq][col]);
                bf[nf][1] = __float_as_uint(Bs[s][kb + cq + 4][col]);
            }
            #pragma unroll
            for (int mf = 0; mf < 4; mf++) {
                int row0 = warp_m * 64 + mf * 16 + r;
                uint32_t af[4];
                af[0] = __float_as_uint(As[s][kb + cq][row0]);
                af[1] = __float_as_uint(As[s][kb + cq][row0 + 8]);
                af[2] = __float_as_uint(As[s][kb + cq + 4][row0]);
                af[3] = __float_as_uint(As[s][kb + cq + 4][row0 + 8]);
                #pragma unroll
                for (int nf = 0; nf < 4; nf++)
                    mma1688(acc[mf][nf], af, bf[nf]);
            }
        }
        if (c + 1 < NC) {
            stg(s ^ 1, pa0, pa1, pb0, pb1);
            __syncthreads();
        }
    }

    #pragma unroll
    for (int mf = 0; mf < 4; mf++) {
        int row0 = blockIdx.y * 128 + warp_m * 64 + mf * 16 + r;
        #pragma unroll
        for (int nf = 0; nf < 4; nf++) {
            int gcol = blockIdx.x * 128 + warp_n * 32 + nf * 8 + cq * 2;
            float2 bv = *(const float2*)(bias + gcol);
            float2 v0, v1;
            v0.x = acc[mf][nf][0] + bv.x;
            v0.y = acc[mf][nf][1] + bv.y;
            v1.x = acc[mf][nf][2] + bv.x;
            v1.y = acc[mf][nf][3] + bv.y;
            if (MODE == 2) {
                float2 r0 = *(const float2*)(g_xn + (size_t)row0 * 1024 + gcol);
                float2 r1 = *(const float2*)(g_xn + (size_t)(row0 + 8) * 1024 + gcol);
                v0.x += r0.x; v0.y += r0.y;
                v1.x += r1.x; v1.y += r1.y;
            }
            *(float2*)(C + (size_t)row0 * N + gcol)       = v0;
            *(float2*)(C + (size_t)(row0 + 8) * N + gcol) = v1;
        }
    }
}

// ============================================================
// Flash attention on tf32 mma.sync.
// CTA = one (b,h) x 64 q rows. 128 threads = 4 warps, warp = 16 q rows.
// KV tiles of 64. Q frags live in registers (32/thread).
// smem: Ps[64][68] (Q staging then P), Ks[64][68], Vs[64][72].
// ============================================================
#define PQ  68
#define PVW 72
#define ATTN_SMEM ((64*PQ + 64*PQ + 64*PVW) * 4)   // 53248 B

__global__ __launch_bounds__(128)
void attn_mma(const int* __restrict__ lens)
{
    extern __shared__ float sm[];
    float* Ps = sm;                 // [64][PQ]
    float* Ks = sm + 64 * PQ;       // [64][PQ]  (kv x d)
    float* Vs = sm + 2 * 64 * PQ;   // [64][PVW] (kv x d)

    int tid = threadIdx.x;
    int wid = tid >> 5, lane = tid & 31;
    int r = lane >> 2, cq = lane & 3;
    int b = blockIdx.z, h = blockIdx.y, qb = blockIdx.x * 64;
    int len = lens[b];

    // ---- stage Q tile (scaled by 1/8, tf32-rounded)
    {
        int row = tid >> 1, dbase = (tid & 1) * 32;
        const float4* src = (const float4*)(g_q + (size_t)(b * SQL + qb + row) * 1024 + h * 64 + dbase);
        float* dst = Ps + row * PQ + dbase;
        #pragma unroll
        for (int i = 0; i < 8; i++) {
            float4 v = src[i];
            dst[i*4+0] = tf32r(v.x * 0.125f);
            dst[i*4+1] = tf32r(v.y * 0.125f);
            dst[i*4+2] = tf32r(v.z * 0.125f);
            dst[i*4+3] = tf32r(v.w * 0.125f);
        }
    }
    __syncthreads();

    int row0 = wid * 16 + r;
    uint32_t qf[8][4];
    #pragma unroll
    for (int kb = 0; kb < 8; kb++) {
        qf[kb][0] = __float_as_uint(Ps[row0 * PQ + kb*8 + cq]);
        qf[kb][1] = __float_as_uint(Ps[(row0 + 8) * PQ + kb*8 + cq]);
        qf[kb][2] = __float_as_uint(Ps[row0 * PQ + kb*8 + cq + 4]);
        qf[kb][3] = __float_as_uint(Ps[(row0 + 8) * PQ + kb*8 + cq + 4]);
    }

    float oacc[8][4];
    #pragma unroll
    for (int i = 0; i < 8; i++) { oacc[i][0]=0.f; oacc[i][1]=0.f; oacc[i][2]=0.f; oacc[i][3]=0.f; }
    float m0 = -1e30f, m1 = -1e30f, l0 = 0.f, l1 = 0.f;

    int q_r  = qb + row0;
    int q_r8 = q_r + 8;
    int qmin = qb + wid * 16;

    int kend = min(len, qb + 64);
    for (int t0 = 0; t0 < kend; t0 += 64) {
        __syncthreads();   // all warps done reading previous Ks/Vs
        {
            int kv = tid >> 1, dbase = (tid & 1) * 32;
            const float* src = g_kv + (size_t)(b * SQL + t0 + kv) * 2048 + h * 64 + dbase;
            float* kd = Ks + kv * PQ + dbase;
            float* vd = Vs + kv * PVW + dbase;
            #pragma unroll
            for (int i = 0; i < 8; i++) {
                float4 kk = *(const float4*)(src + i*4);
                float4 o;
                o.x = tf32r(kk.x); o.y = tf32r(kk.y); o.z = tf32r(kk.z); o.w = tf32r(kk.w);
                *(float4*)(kd + i*4) = o;
            }
            #pragma unroll
            for (int i = 0; i < 8; i++) {
                float4 vv = *(const float4*)(src + 1024 + i*4);
                float4 o;
                o.x = tf32r(vv.x); o.y = tf32r(vv.y); o.z = tf32r(vv.z); o.w = tf32r(vv.w);
                *(float4*)(vd + i*4) = o;
            }
        }
        __syncthreads();

        // ---- S = Q K^T   (n = kv, k = d; B read from Ks[kv][d])
        float sacc[8][4];
        #pragma unroll
        for (int i = 0; i < 8; i++) { sacc[i][0]=0.f; sacc[i][1]=0.f; sacc[i][2]=0.f; sacc[i][3]=0.f; }
        #pragma unroll
        for (int kb = 0; kb < 8; kb++) {
            uint32_t bf[8][2];
            #pragma unroll
            for (int nf = 0; nf < 8; nf++) {
                bf[nf][0] = __float_as_uint(Ks[(nf*8 + r) * PQ + kb*8 + cq]);
                bf[nf][1] = __float_as_uint(Ks[(nf*8 + r) * PQ + kb*8 + cq + 4]);
            }
            #pragma unroll
            for (int nf = 0; nf < 8; nf++)
                mma1688(sacc[nf], qf[kb], bf[nf]);
        }

        // ---- mask (warp-uniform fast path for interior tiles)
        bool nomask = (t0 + 63 <= qmin) && (t0 + 64 <= len);
        if (!nomask) {
            #pragma unroll
            for (int nf = 0; nf < 8; nf++) {
                int c0 = t0 + nf*8 + 2*cq, c1 = c0 + 1;
                if (c0 > q_r  || c0 >= len) sacc[nf][0] = -1e30f;
                if (c1 > q_r  || c1 >= len) sacc[nf][1] = -1e30f;
                if (c0 > q_r8 || c0 >= len) sacc[nf][2] = -1e30f;
                if (c1 > q_r8 || c1 >= len) sacc[nf][3] = -1e30f;
            }
        }

        // ---- online softmax (row = quad of 4 lanes)
        float tm0 = -1e30f, tm1 = -1e30f;
        #pragma unroll
        for (int nf = 0; nf < 8; nf++) {
            tm0 = fmaxf(tm0, fmaxf(sacc[nf][0], sacc[nf][1]));
            tm1 = fmaxf(tm1, fmaxf(sacc[nf][2], sacc[nf][3]));
        }
        tm0 = fmaxf(tm0, __shfl_xor_sync(0xffffffffu, tm0, 1));
        tm0 = fmaxf(tm0, __shfl_xor_sync(0xffffffffu, tm0, 2));
        tm1 = fmaxf(tm1, __shfl_xor_sync(0xffffffffu, tm1, 1));
        tm1 = fmaxf(tm1, __shfl_xor_sync(0xffffffffu, tm1, 2));
        float nm0 = fmaxf(m0, tm0), nm1 = fmaxf(m1, tm1);
        float corr0 = __expf(m0 - nm0), corr1 = __expf(m1 - nm1);
        m0 = nm0; m1 = nm1;
        l0 *= corr0; l1 *= corr1;
        #pragma unroll
        for (int nf = 0; nf < 8; nf++) {
            oacc[nf][0] *= corr0; oacc[nf][1] *= corr0;
            oacc[nf][2] *= corr1; oacc[nf][3] *= corr1;
        }
        #pragma unroll
        for (int nf = 0; nf < 8; nf++) {
            float p0 = __expf(sacc[nf][0] - m0);
            float p1 = __expf(sacc[nf][1] - m0);
            float p2 = __expf(sacc[nf][2] - m1);
            float p3 = __expf(sacc[nf][3] - m1);
            l0 += p0 + p1; l1 += p2 + p3;
            float2 lo = make_float2(tf32r(p0), tf32r(p1));
            float2 hi = make_float2(tf32r(p2), tf32r(p3));
            *(float2*)&Ps[row0 * PQ + nf*8 + 2*cq]       = lo;
            *(float2*)&Ps[(row0 + 8) * PQ + nf*8 + 2*cq] = hi;
        }
        __syncwarp();   // Ps rows are warp-private; warp-level visibility suffices

        // ---- O += P V   (A = P from Ps, B = V from Vs[kv][d])
        #pragma unroll
        for (int kb = 0; kb < 8; kb++) {
            uint32_t af[4];
            af[0] = __float_as_uint(Ps[row0 * PQ + kb*8 + cq]);
            af[1] = __float_as_uint(Ps[(row0 + 8) * PQ + kb*8 + cq]);
            af[2] = __float_as_uint(Ps[row0 * PQ + kb*8 + cq + 4]);
            af[3] = __float_as_uint(Ps[(row0 + 8) * PQ + kb*8 + cq + 4]);
            uint32_t bf[8][2];
            #pragma unroll
            for (int nf = 0; nf < 8; nf++) {
                bf[nf][0] = __float_as_uint(Vs[(kb*8 + cq) * PVW + nf*8 + r]);
                bf[nf][1] = __float_as_uint(Vs[(kb*8 + cq + 4) * PVW + nf*8 + r]);
            }
            #pragma unroll
            for (int nf = 0; nf < 8; nf++)
                mma1688(oacc[nf], af, bf[nf]);
        }
    }

    // ---- epilogue: reduce l over the quad, normalize, store
    l0 += __shfl_xor_sync(0xffffffffu, l0, 1);
    l0 += __shfl_xor_sync(0xffffffffu, l0, 2);
    l1 += __shfl_xor_sync(0xffffffffu, l1, 1);
    l1 += __shfl_xor_sync(0xffffffffu, l1, 2);
    float i0 = 1.f / l0, i1 = 1.f / l1;
    float* o0 = g_att + (size_t)(b * SQL + q_r)  * 1024 + h * 64;
    float* o1 = g_att + (size_t)(b * SQL + q_r8) * 1024 + h * 64;
    #pragma unroll
    for (int nf = 0; nf < 8; nf++) {
        *(float2*)&o0[nf*8 + 2*cq] = make_float2(oacc[nf][0] * i0, oacc[nf][1] * i0);
        *(float2*)&o1[nf*8 + 2*cq] = make_float2(oacc[nf][2] * i1, oacc[nf][3] * i1);
    }
}

// ============================================================
// Launch
// ============================================================
extern "C" void kernel_launch(void* const* d_in, const int* in_sizes, int n_in,
                              void* d_out, int out_size)
{
    const float* x    = (const float*)d_in[0];
    // d_in[1] == key_value_sequences, identical to x (self-attention path)
    const int*   lens = (const int*)  d_in[2];
    const float* Wq   = (const float*)d_in[3];
    const float* bq   = (const float*)d_in[4];
    const float* Wkv  = (const float*)d_in[5];
    const float* bkv  = (const float*)d_in[6];
    const float* Wo   = (const float*)d_in[7];
    const float* bo   = (const float*)d_in[8];
    const float* gam  = (const float*)d_in[9];
    const float* bet  = (const float*)d_in[10];
    float* out = (float*)d_out;

    cudaFuncSetAttribute(attn_mma, cudaFuncAttributeMaxDynamicSharedMemorySize, ATTN_SMEM);

    // 1. LayerNorm (shared by q and kv paths)
    ln_kernel<<<ROWS, 256>>>(x, gam, bet);
    // 2. transpose + tf32-round the weights
    transpose_rna<0><<<dim3(32, 32), dim3(32, 8)>>>(Wq, 1024);
    transpose_rna<1><<<dim3(64, 32), dim3(32, 8)>>>(Wkv, 2048);
    transpose_rna<2><<<dim3(32, 32), dim3(32, 8)>>>(Wo, 1024);
    // 3. projections on mma.sync tf32
    mma_gemm<0><<<dim3(8, 64),  256>>>(bq,  nullptr, 1024);
    mma_gemm<1><<<dim3(16, 64), 256>>>(bkv, nullptr, 2048);
    // 4. flash attention on tensor cores (causal + padding)
    attn_mma<<<dim3(16, 16, 8), 128, ATTN_SMEM>>>(lens);
    // 5. out = att @ Wo + bo + residual(xn)
    mma_gemm<2><<<dim3(8, 64),  256>>>(bo, out, 1024);
}

// round 10
// speedup vs baseline: 4.5129x; 1.1180x over previous
#include <cuda_runtime.h>
#include <cstdint>

typedef unsigned long long ull;

// Problem constants
#define BB   8
#define SQL  1024
#define DMOD 1024
#define ROWS (BB*SQL)   // 8192

// Scratch (device globals; no allocation allowed)
__device__ float g_xn  [ROWS * DMOD];    // LayerNorm(x) fp32 (also residual)
__device__ float g_q   [ROWS * DMOD];    // Q projection
__device__ float g_kv  [ROWS * 2048];    // K cols 0..1023, V cols 1024..2047
__device__ float g_att [ROWS * DMOD];    // attention out
__device__ float g_wqt [1024 * 1024];    // Wq^T  [N,K] tf32-rounded
__device__ float g_wkvt[2048 * 1024];    // Wkv^T [N,K] tf32-rounded
__device__ float g_wot [1024 * 1024];    // Wo^T  [N,K] tf32-rounded

// ---------------- helpers ----------------
__device__ __forceinline__ float tf32r(float x) {
    uint32_t u; asm("cvt.rna.tf32.f32 %0, %1;" : "=r"(u) : "f"(x));
    return __uint_as_float(u);
}
__device__ __forceinline__ uint32_t smem_u32(const void* p) {
    uint32_t a;
    asm("{ .reg .u64 t; cvta.to.shared.u64 t, %1; cvt.u32.u64 %0, t; }" : "=r"(a) : "l"(p));
    return a;
}
// mma.sync m16n8k8 tf32 (compiles to HMMA on base sm_103 target)
__device__ __forceinline__ void mma1688(float* c, const uint32_t* a, const uint32_t* b) {
    asm volatile(
        "mma.sync.aligned.m16n8k8.row.col.f32.tf32.tf32.f32 "
        "{%0,%1,%2,%3}, {%4,%5,%6,%7}, {%8,%9}, {%0,%1,%2,%3};"
        : "+f"(c[0]), "+f"(c[1]), "+f"(c[2]), "+f"(c[3])
        : "r"(a[0]), "r"(a[1]), "r"(a[2]), "r"(a[3]), "r"(b[0]), "r"(b[1]));
}

// ============================================================
// LayerNorm: one block per row (1024 elems), 256 threads
// ============================================================
__global__ void ln_kernel(const float* __restrict__ x,
                          const float* __restrict__ gam,
                          const float* __restrict__ bet)
{
    int row = blockIdx.x, tid = threadIdx.x;
    const float4* xr = (const float4*)(x + (size_t)row * DMOD);
    float4 v = xr[tid];
    float s  = v.x + v.y + v.z + v.w;
    float ss = v.x*v.x + v.y*v.y + v.z*v.z + v.w*v.w;
    #pragma unroll
    for (int o = 16; o > 0; o >>= 1) {
        s  += __shfl_down_sync(0xffffffffu, s,  o);
        ss += __shfl_down_sync(0xffffffffu, ss, o);
    }
    __shared__ float sh[2][8];
    __shared__ float res[2];
    int wid = tid >> 5, lane = tid & 31;
    if (lane == 0) { sh[0][wid] = s; sh[1][wid] = ss; }
    __syncthreads();
    if (tid == 0) {
        float a = 0.f, b = 0.f;
        #pragma unroll
        for (int i = 0; i < 8; i++) { a += sh[0][i]; b += sh[1][i]; }
        float mean = a * (1.f / 1024.f);
        float var  = b * (1.f / 1024.f) - mean * mean;
        res[0] = mean;
        res[1] = rsqrtf(var + 1e-3f);
    }
    __syncthreads();
    float mean = res[0], rstd = res[1];
    float4 g4 = ((const float4*)gam)[tid];
    float4 b4 = ((const float4*)bet)[tid];
    float4 o;
    o.x = (v.x - mean) * rstd * g4.x + b4.x;
    o.y = (v.y - mean) * rstd * g4.y + b4.y;
    o.z = (v.z - mean) * rstd * g4.z + b4.z;
    o.w = (v.w - mean) * rstd * g4.w + b4.w;
    ((float4*)(g_xn + (size_t)row * DMOD))[tid] = o;
}

// ============================================================
// Weight transpose + round-to-nearest tf32.
// ============================================================
template<int W>
__global__ void transpose_rna(const float* __restrict__ Wm, int N)
{
    float* WT = (W == 0) ? g_wqt : (W == 1) ? g_wkvt : g_wot;
    __shared__ float t[32][33];
    int bn = blockIdx.x * 32, bk = blockIdx.y * 32;
    int x = threadIdx.x, y = threadIdx.y;
    #pragma unroll
    for (int i = 0; i < 4; i++)
        t[y + i*8][x] = Wm[(size_t)(bk + y + i*8) * N + bn + x];
    __syncthreads();
    #pragma unroll
    for (int i = 0; i < 4; i++)
        WT[(size_t)(bn + y + i*8) * 1024 + bk + x] = tf32r(t[x][y + i*8]);
}

// ============================================================
// tf32 mma.sync GEMM. CTA tile 128x128, K chunks of 16, double-buffered.
// ============================================================
#define PAD 136

template<int MODE>
__global__ __launch_bounds__(256, 2)
void mma_gemm(const float* __restrict__ bias, float* __restrict__ Cout, int N)
{
    const float* A  = (MODE == 2) ? g_att : g_xn;
    const float* Bt = (MODE == 0) ? g_wqt : (MODE == 1) ? g_wkvt : g_wot;
    float* C = (MODE == 0) ? g_q : (MODE == 1) ? g_kv : Cout;

    __shared__ float As[2][16][PAD];
    __shared__ float Bs[2][16][PAD];

    int tid = threadIdx.x;
    int wid = tid >> 5, lane = tid & 31;
    int warp_m = wid & 1, warp_n = wid >> 1;
    int r = lane >> 2, cq = lane & 3;

    int lr = tid >> 1;
    int lc = (tid & 1) * 8;
    const float* Ap = A  + (size_t)(blockIdx.y * 128 + lr) * 1024 + lc;
    const float* Bp = Bt + (size_t)(blockIdx.x * 128 + lr) * 1024 + lc;

    float acc[4][4][4];
    #pragma unroll
    for (int i = 0; i < 4; i++)
        #pragma unroll
        for (int j = 0; j < 4; j++)
            #pragma unroll
            for (int k = 0; k < 4; k++) acc[i][j][k] = 0.f;

    float4 pa0 = *(const float4*)(Ap);
    float4 pa1 = *(const float4*)(Ap + 4);
    float4 pb0 = *(const float4*)(Bp);
    float4 pb1 = *(const float4*)(Bp + 4);

    auto stg = [&](int s, float4 a0, float4 a1, float4 b0, float4 b1) {
        float* da = &As[s][lc][lr];
        da[0*PAD] = tf32r(a0.x); da[1*PAD] = tf32r(a0.y);
        da[2*PAD] = tf32r(a0.z); da[3*PAD] = tf32r(a0.w);
        da[4*PAD] = tf32r(a1.x); da[5*PAD] = tf32r(a1.y);
        da[6*PAD] = tf32r(a1.z); da[7*PAD] = tf32r(a1.w);
        float* db = &Bs[s][lc][lr];
        db[0*PAD] = tf32r(b0.x); db[1*PAD] = tf32r(b0.y);
        db[2*PAD] = tf32r(b0.z); db[3*PAD] = tf32r(b0.w);
        db[4*PAD] = tf32r(b1.x); db[5*PAD] = tf32r(b1.y);
        db[6*PAD] = tf32r(b1.z); db[7*PAD] = tf32r(b1.w);
    };

    stg(0, pa0, pa1, pb0, pb1);
    __syncthreads();

    const int NC = 64;
    for (int c = 0; c < NC; c++) {
        int s = c & 1;
        if (c + 1 < NC) {
            const float* ap = Ap + (c + 1) * 16;
            const float* bp = Bp + (c + 1) * 16;
            pa0 = *(const float4*)(ap);
            pa1 = *(const float4*)(ap + 4);
            pb0 = *(const float4*)(bp);
            pb1 = *(const float4*)(bp + 4);
        }
        #pragma unroll
        for (int ks = 0; ks < 2; ks++) {
            int kb = ks * 8;
            uint32_t bf[4][2];
            #pragma unroll
            for (int nf = 0; nf < 4; nf++) {
                int col = warp_n * 32 + nf * 8 + r;
                bf[nf][0] = __float_as_uint(Bs[s][kb + cq][col]);
                bf[nf][1] = __float_as_uint(Bs[s][kb + cq + 4][col]);
            }
            #pragma unroll
            for (int mf = 0; mf < 4; mf++) {
                int row0 = warp_m * 64 + mf * 16 + r;
                uint32_t af[4];
                af[0] = __float_as_uint(As[s][kb + cq][row0]);
                af[1] = __float_as_uint(As[s][kb + cq][row0 + 8]);
                af[2] = __float_as_uint(As[s][kb + cq + 4][row0]);
                af[3] = __float_as_uint(As[s][kb + cq + 4][row0 + 8]);
                #pragma unroll
                for (int nf = 0; nf < 4; nf++)
                    mma1688(acc[mf][nf], af, bf[nf]);
            }
        }
        if (c + 1 < NC) {
            stg(s ^ 1, pa0, pa1, pb0, pb1);
            __syncthreads();
        }
    }

    #pragma unroll
    for (int mf = 0; mf < 4; mf++) {
        int row0 = blockIdx.y * 128 + warp_m * 64 + mf * 16 + r;
        #pragma unroll
        for (int nf = 0; nf < 4; nf++) {
            int gcol = blockIdx.x * 128 + warp_n * 32 + nf * 8 + cq * 2;
            float2 bv = *(const float2*)(bias + gcol);
            float2 v0, v1;
            v0.x = acc[mf][nf][0] + bv.x;
            v0.y = acc[mf][nf][1] + bv.y;
            v1.x = acc[mf][nf][2] + bv.x;
            v1.y = acc[mf][nf][3] + bv.y;
            if (MODE == 2) {
                float2 r0 = *(const float2*)(g_xn + (size_t)row0 * 1024 + gcol);
                float2 r1 = *(const float2*)(g_xn + (size_t)(row0 + 8) * 1024 + gcol);
                v0.x += r0.x; v0.y += r0.y;
                v1.x += r1.x; v1.y += r1.y;
            }
            *(float2*)(C + (size_t)row0 * N + gcol)       = v0;
            *(float2*)(C + (size_t)(row0 + 8) * N + gcol) = v1;
        }
    }
}

// ============================================================
// Flash attention on tf32 mma.sync, cp.async double-buffered KV.
// CTA = one (b,h) x 128 q rows. 256 threads = 8 warps, warp = 16 q rows.
// KV tiles of 64. K/V fed raw fp32 (HMMA HW-truncates to tf32);
// Q and P rna-rounded.
// smem: Ps[128][68] (Q staging then P), Ks[2][64][68], Vs[2][64][72].
// ============================================================
#define PQ  68
#define PK  68
#define PV  72
#define ATTN_SMEM ((128*PQ + 2*64*PK + 2*64*PV) * 4)   // 106496 B

__global__ __launch_bounds__(256)
void attn_mma(const int* __restrict__ lens)
{
    extern __shared__ float sm[];
    float* Ps = sm;                          // [128][PQ]
    float* Ks = sm + 128 * PQ;               // [2][64][PK]
    float* Vs = sm + 128 * PQ + 2 * 64 * PK; // [2][64][PV]

    int tid = threadIdx.x;
    int wid = tid >> 5, lane = tid & 31;
    int r = lane >> 2, cq = lane & 3;
    int b = blockIdx.z, h = blockIdx.y, qb = blockIdx.x * 128;
    int len = lens[b];

    uint32_t ks_base = smem_u32(Ks);
    uint32_t vs_base = smem_u32(Vs);

    // cp.async loader: 4 threads per kv row, each thread 64B of K + 64B of V
    int kvr = tid >> 2, loff = (tid & 3) * 16;
    const float* gsrc = g_kv + (size_t)(b * SQL) * 2048 + h * 64;

    auto issue = [&](int t0, int s) {
        const float* gk = gsrc + (size_t)(t0 + kvr) * 2048 + loff;
        const float* gv = gk + 1024;
        uint32_t dk = ks_base + (uint32_t)(s * 64 * PK + kvr * PK + loff) * 4u;
        uint32_t dv = vs_base + (uint32_t)(s * 64 * PV + kvr * PV + loff) * 4u;
        #pragma unroll
        for (int i = 0; i < 4; i++)
            asm volatile("cp.async.ca.shared.global [%0], [%1], 16;"
                         :: "r"(dk + i * 16), "l"(gk + i * 4));
        #pragma unroll
        for (int i = 0; i < 4; i++)
            asm volatile("cp.async.ca.shared.global [%0], [%1], 16;"
                         :: "r"(dv + i * 16), "l"(gv + i * 4));
        asm volatile("cp.async.commit_group;" ::: "memory");
    };

    issue(0, 0);   // prefetch tile 0 while we stage Q

    // ---- stage Q tile (scaled by 1/8, tf32 rna)
    {
        int row = tid >> 1, dbase = (tid & 1) * 32;
        const float4* src = (const float4*)(g_q + (size_t)(b * SQL + qb + row) * 1024 + h * 64 + dbase);
        float* dst = Ps + row * PQ + dbase;
        #pragma unroll
        for (int i = 0; i < 8; i++) {
            float4 v = src[i];
            dst[i*4+0] = tf32r(v.x * 0.125f);
            dst[i*4+1] = tf32r(v.y * 0.125f);
            dst[i*4+2] = tf32r(v.z * 0.125f);
            dst[i*4+3] = tf32r(v.w * 0.125f);
        }
    }
    __syncthreads();

    int row0 = wid * 16 + r;
    uint32_t qf[8][4];
    #pragma unroll
    for (int kb = 0; kb < 8; kb++) {
        qf[kb][0] = __float_as_uint(Ps[row0 * PQ + kb*8 + cq]);
        qf[kb][1] = __float_as_uint(Ps[(row0 + 8) * PQ + kb*8 + cq]);
        qf[kb][2] = __float_as_uint(Ps[row0 * PQ + kb*8 + cq + 4]);
        qf[kb][3] = __float_as_uint(Ps[(row0 + 8) * PQ + kb*8 + cq + 4]);
    }

    float oacc[8][4];
    #pragma unroll
    for (int i = 0; i < 8; i++) { oacc[i][0]=0.f; oacc[i][1]=0.f; oacc[i][2]=0.f; oacc[i][3]=0.f; }
    float m0 = -1e30f, m1 = -1e30f, l0 = 0.f, l1 = 0.f;

    int q_r  = qb + row0;
    int q_r8 = q_r + 8;
    int qmin = qb + wid * 16;
    int qmax = qmin + 15;

    int kend = min(len, qb + 128);
    int T = (kend + 63) >> 6;

    for (int t = 0; t < T; t++) {
        int s = t & 1;
        int t0 = t * 64;
        if (t + 1 < T) {
            issue((t + 1) * 64, s ^ 1);
            asm volatile("cp.async.wait_group 1;" ::: "memory");
        } else {
            asm volatile("cp.async.wait_group 0;" ::: "memory");
        }
        __syncthreads();   // tile t data visible to all threads

        const float* Kc = Ks + s * 64 * PK;
        const float* Vc = Vs + s * 64 * PV;

        if (t0 <= qmax) {   // skip tiles entirely in this warp's causal future
            // ---- S = Q K^T
            float sacc[8][4];
            #pragma unroll
            for (int i = 0; i < 8; i++) { sacc[i][0]=0.f; sacc[i][1]=0.f; sacc[i][2]=0.f; sacc[i][3]=0.f; }
            #pragma unroll
            for (int kb = 0; kb < 8; kb++) {
                uint32_t bf[8][2];
                #pragma unroll
                for (int nf = 0; nf < 8; nf++) {
                    bf[nf][0] = __float_as_uint(Kc[(nf*8 + r) * PK + kb*8 + cq]);
                    bf[nf][1] = __float_as_uint(Kc[(nf*8 + r) * PK + kb*8 + cq + 4]);
                }
                #pragma unroll
                for (int nf = 0; nf < 8; nf++)
                    mma1688(sacc[nf], qf[kb], bf[nf]);
            }

            // ---- mask (warp-uniform fast path for interior tiles)
            bool nomask = (t0 + 63 <= qmin) && (t0 + 64 <= len);
            if (!nomask) {
                #pragma unroll
                for (int nf = 0; nf < 8; nf++) {
                    int c0 = t0 + nf*8 + 2*cq, c1 = c0 + 1;
                    if (c0 > q_r  || c0 >= len) sacc[nf][0] = -1e30f;
                    if (c1 > q_r  || c1 >= len) sacc[nf][1] = -1e30f;
                    if (c0 > q_r8 || c0 >= len) sacc[nf][2] = -1e30f;
                    if (c1 > q_r8 || c1 >= len) sacc[nf][3] = -1e30f;
                }
            }

            // ---- online softmax (row = quad of 4 lanes)
            float tm0 = -1e30f, tm1 = -1e30f;
            #pragma unroll
            for (int nf = 0; nf < 8; nf++) {
                tm0 = fmaxf(tm0, fmaxf(sacc[nf][0], sacc[nf][1]));
                tm1 = fmaxf(tm1, fmaxf(sacc[nf][2], sacc[nf][3]));
            }
            tm0 = fmaxf(tm0, __shfl_xor_sync(0xffffffffu, tm0, 1));
            tm0 = fmaxf(tm0, __shfl_xor_sync(0xffffffffu, tm0, 2));
            tm1 = fmaxf(tm1, __shfl_xor_sync(0xffffffffu, tm1, 1));
            tm1 = fmaxf(tm1, __shfl_xor_sync(0xffffffffu, tm1, 2));
            float nm0 = fmaxf(m0, tm0), nm1 = fmaxf(m1, tm1);
            float corr0 = __expf(m0 - nm0), corr1 = __expf(m1 - nm1);
            m0 = nm0; m1 = nm1;
            l0 *= corr0; l1 *= corr1;
            #pragma unroll
            for (int nf = 0; nf < 8; nf++) {
                oacc[nf][0] *= corr0; oacc[nf][1] *= corr0;
                oacc[nf][2] *= corr1; oacc[nf][3] *= corr1;
            }
            #pragma unroll
            for (int nf = 0; nf < 8; nf++) {
                float p0 = __expf(sacc[nf][0] - m0);
                float p1 = __expf(sacc[nf][1] - m0);
                float p2 = __expf(sacc[nf][2] - m1);
                float p3 = __expf(sacc[nf][3] - m1);
                l0 += p0 + p1; l1 += p2 + p3;
                float2 lo = make_float2(tf32r(p0), tf32r(p1));
                float2 hi = make_float2(tf32r(p2), tf32r(p3));
                *(float2*)&Ps[row0 * PQ + nf*8 + 2*cq]       = lo;
                *(float2*)&Ps[(row0 + 8) * PQ + nf*8 + 2*cq] = hi;
            }
            __syncwarp();   // Ps rows are warp-private

            // ---- O += P V
            #pragma unroll
            for (int kb = 0; kb < 8; kb++) {
                uint32_t af[4];
                af[0] = __float_as_uint(Ps[row0 * PQ + kb*8 + cq]);
                af[1] = __float_as_uint(Ps[(row0 + 8) * PQ + kb*8 + cq]);
                af[2] = __float_as_uint(Ps[row0 * PQ + kb*8 + cq + 4]);
                af[3] = __float_as_uint(Ps[(row0 + 8) * PQ + kb*8 + cq + 4]);
                uint32_t bf[8][2];
                #pragma unroll
                for (int nf = 0; nf < 8; nf++) {
                    bf[nf][0] = __float_as_uint(Vc[(kb*8 + cq) * PV + nf*8 + r]);
                    bf[nf][1] = __float_as_uint(Vc[(kb*8 + cq + 4) * PV + nf*8 + r]);
                }
                #pragma unroll
                for (int nf = 0; nf < 8; nf++)
                    mma1688(oacc[nf], af, bf[nf]);
            }
        }
        __syncthreads();   // all warps done with buf s before it is refilled
    }

    // ---- epilogue
    l0 += __shfl_xor_sync(0xffffffffu, l0, 1);
    l0 += __shfl_xor_sync(0xffffffffu, l0, 2);
    l1 += __shfl_xor_sync(0xffffffffu, l1, 1);
    l1 += __shfl_xor_sync(0xffffffffu, l1, 2);
    float i0 = 1.f / l0, i1 = 1.f / l1;
    float* o0 = g_att + (size_t)(b * SQL + q_r)  * 1024 + h * 64;
    float* o1 = g_att + (size_t)(b * SQL + q_r8) * 1024 + h * 64;
    #pragma unroll
    for (int nf = 0; nf < 8; nf++) {
        *(float2*)&o0[nf*8 + 2*cq] = make_float2(oacc[nf][0] * i0, oacc[nf][1] * i0);
        *(float2*)&o1[nf*8 + 2*cq] = make_float2(oacc[nf][2] * i1, oacc[nf][3] * i1);
    }
}

// ============================================================
// Launch
// ============================================================
extern "C" void kernel_launch(void* const* d_in, const int* in_sizes, int n_in,
                              void* d_out, int out_size)
{
    const float* x    = (const float*)d_in[0];
    // d_in[1] == key_value_sequences, identical to x (self-attention path)
    const int*   lens = (const int*)  d_in[2];
    const float* Wq   = (const float*)d_in[3];
    const float* bq   = (const float*)d_in[4];
    const float* Wkv  = (const float*)d_in[5];
    const float* bkv  = (const float*)d_in[6];
    const float* Wo   = (const float*)d_in[7];
    const float* bo   = (const float*)d_in[8];
    const float* gam  = (const float*)d_in[9];
    const float* bet  = (const float*)d_in[10];
    float* out = (float*)d_out;

    cudaFuncSetAttribute(attn_mma, cudaFuncAttributeMaxDynamicSharedMemorySize, ATTN_SMEM);

    // 1. LayerNorm (shared by q and kv paths)
    ln_kernel<<<ROWS, 256>>>(x, gam, bet);
    // 2. transpose + tf32-round the weights
    transpose_rna<0><<<dim3(32, 32), dim3(32, 8)>>>(Wq, 1024);
    transpose_rna<1><<<dim3(64, 32), dim3(32, 8)>>>(Wkv, 2048);
    transpose_rna<2><<<dim3(32, 32), dim3(32, 8)>>>(Wo, 1024);
    // 3. projections on mma.sync tf32
    mma_gemm<0><<<dim3(8, 64),  256>>>(bq,  nullptr, 1024);
    mma_gemm<1><<<dim3(16, 64), 256>>>(bkv, nullptr, 2048);
    // 4. flash attention on tensor cores (causal + padding), pipelined KV
    attn_mma<<<dim3(8, 16, 8), 256, ATTN_SMEM>>>(lens);
    // 5. out = att @ Wo + bo + residual(xn)
    mma_gemm<2><<<dim3(8, 64),  256>>>(bo, out, 1024);
}

// round 13
// speedup vs baseline: 4.5719x; 1.0131x over previous
#include <cuda_runtime.h>
#include <cstdint>

typedef unsigned long long ull;

// Problem constants
#define BB   8
#define SQL  1024
#define DMOD 1024
#define ROWS (BB*SQL)   // 8192

// Scratch (device globals; no allocation allowed)
__device__ float g_xn  [ROWS * DMOD];    // LayerNorm(x) fp32 (also residual)
__device__ float g_q   [ROWS * DMOD];    // Q projection
__device__ float g_kv  [ROWS * 2048];    // K cols 0..1023, V cols 1024..2047
__device__ float g_att [ROWS * DMOD];    // attention out
__device__ float g_wqt [1024 * 1024];    // Wq^T  [N,K] tf32-rounded
__device__ float g_wkvt[2048 * 1024];    // Wkv^T [N,K] tf32-rounded
__device__ float g_wot [1024 * 1024];    // Wo^T  [N,K] tf32-rounded

// ---------------- helpers ----------------
__device__ __forceinline__ float tf32r(float x) {
    uint32_t u; asm("cvt.rna.tf32.f32 %0, %1;" : "=r"(u) : "f"(x));
    return __uint_as_float(u);
}
__device__ __forceinline__ float ex2f(float x) {
    float r; asm("ex2.approx.f32 %0, %1;" : "=f"(r) : "f"(x)); return r;
}
__device__ __forceinline__ uint32_t smem_u32(const void* p) {
    uint32_t a;
    asm("{ .reg .u64 t; cvta.to.shared.u64 t, %1; cvt.u32.u64 %0, t; }" : "=r"(a) : "l"(p));
    return a;
}
// mma.sync m16n8k8 tf32 (compiles to HMMA on base sm_103 target)
__device__ __forceinline__ void mma1688(float* c, const uint32_t* a, const uint32_t* b) {
    asm volatile(
        "mma.sync.aligned.m16n8k8.row.col.f32.tf32.tf32.f32 "
        "{%0,%1,%2,%3}, {%4,%5,%6,%7}, {%8,%9}, {%0,%1,%2,%3};"
        : "+f"(c[0]), "+f"(c[1]), "+f"(c[2]), "+f"(c[3])
        : "r"(a[0]), "r"(a[1]), "r"(a[2]), "r"(a[3]), "r"(b[0]), "r"(b[1]));
}
// ldmatrix x4 (b16): for tf32 data one m8n8.b16 tile is an 8x4 float tile;
// thread lane receives (row = lane/4, word-col = lane%4) of each matrix.
// NOTE: "memory" clobber is required — smem stores precede these reads.
__device__ __forceinline__ void ldm4(uint32_t* r, uint32_t addr) {
    asm volatile("ldmatrix.sync.aligned.m8n8.x4.shared.b16 {%0,%1,%2,%3}, [%4];"
        : "=r"(r[0]), "=r"(r[1]), "=r"(r[2]), "=r"(r[3]) : "r"(addr) : "memory");
}

// ============================================================
// LayerNorm: one block per row (1024 elems), 256 threads
// ============================================================
__global__ void ln_kernel(const float* __restrict__ x,
                          const float* __restrict__ gam,
                          const float* __restrict__ bet)
{
    int row = blockIdx.x, tid = threadIdx.x;
    const float4* xr = (const float4*)(x + (size_t)row * DMOD);
    float4 v = xr[tid];
    float s  = v.x + v.y + v.z + v.w;
    float ss = v.x*v.x + v.y*v.y + v.z*v.z + v.w*v.w;
    #pragma unroll
    for (int o = 16; o > 0; o >>= 1) {
        s  += __shfl_down_sync(0xffffffffu, s,  o);
        ss += __shfl_down_sync(0xffffffffu, ss, o);
    }
    __shared__ float sh[2][8];
    __shared__ float res[2];
    int wid = tid >> 5, lane = tid & 31;
    if (lane == 0) { sh[0][wid] = s; sh[1][wid] = ss; }
    __syncthreads();
    if (tid == 0) {
        float a = 0.f, b = 0.f;
        #pragma unroll
        for (int i = 0; i < 8; i++) { a += sh[0][i]; b += sh[1][i]; }
        float mean = a * (1.f / 1024.f);
        float var  = b * (1.f / 1024.f) - mean * mean;
        res[0] = mean;
        res[1] = rsqrtf(var + 1e-3f);
    }
    __syncthreads();
    float mean = res[0], rstd = res[1];
    float4 g4 = ((const float4*)gam)[tid];
    float4 b4 = ((const float4*)bet)[tid];
    float4 o;
    o.x = (v.x - mean) * rstd * g4.x + b4.x;
    o.y = (v.y - mean) * rstd * g4.y + b4.y;
    o.z = (v.z - mean) * rstd * g4.z + b4.z;
    o.w = (v.w - mean) * rstd * g4.w + b4.w;
    ((float4*)(g_xn + (size_t)row * DMOD))[tid] = o;
}

// ============================================================
// Weight transpose + round-to-nearest tf32.
// ============================================================
template<int W>
__global__ void transpose_rna(const float* __restrict__ Wm, int N)
{
    float* WT = (W == 0) ? g_wqt : (W == 1) ? g_wkvt : g_wot;
    __shared__ float t[32][33];
    int bn = blockIdx.x * 32, bk = blockIdx.y * 32;
    int x = threadIdx.x, y = threadIdx.y;
    #pragma unroll
    for (int i = 0; i < 4; i++)
        t[y + i*8][x] = Wm[(size_t)(bk + y + i*8) * N + bn + x];
    __syncthreads();
    #pragma unroll
    for (int i = 0; i < 4; i++)
        WT[(size_t)(bn + y + i*8) * 1024 + bk + x] = tf32r(t[x][y + i*8]);
}

// ============================================================
// tf32 mma.sync GEMM. CTA tile 128x128, K chunks of 16, double-buffered.
// ============================================================
#define PAD 136

template<int MODE>
__global__ __launch_bounds__(256, 2)
void mma_gemm(const float* __restrict__ bias, float* __restrict__ Cout, int N)
{
    const float* A  = (MODE == 2) ? g_att : g_xn;
    const float* Bt = (MODE == 0) ? g_wqt : (MODE == 1) ? g_wkvt : g_wot;
    float* C = (MODE == 0) ? g_q : (MODE == 1) ? g_kv : Cout;

    __shared__ float As[2][16][PAD];
    __shared__ float Bs[2][16][PAD];

    int tid = threadIdx.x;
    int wid = tid >> 5, lane = tid & 31;
    int warp_m = wid & 1, warp_n = wid >> 1;
    int r = lane >> 2, cq = lane & 3;

    int lr = tid >> 1;
    int lc = (tid & 1) * 8;
    const float* Ap = A  + (size_t)(blockIdx.y * 128 + lr) * 1024 + lc;
    const float* Bp = Bt + (size_t)(blockIdx.x * 128 + lr) * 1024 + lc;

    float acc[4][4][4];
    #pragma unroll
    for (int i = 0; i < 4; i++)
        #pragma unroll
        for (int j = 0; j < 4; j++)
            #pragma unroll
            for (int k = 0; k < 4; k++) acc[i][j][k] = 0.f;

    float4 pa0 = *(const float4*)(Ap);
    float4 pa1 = *(const float4*)(Ap + 4);
    float4 pb0 = *(const float4*)(Bp);
    float4 pb1 = *(const float4*)(Bp + 4);

    auto stg = [&](int s, float4 a0, float4 a1, float4 b0, float4 b1) {
        float* da = &As[s][lc][lr];
        da[0*PAD] = tf32r(a0.x); da[1*PAD] = tf32r(a0.y);
        da[2*PAD] = tf32r(a0.z); da[3*PAD] = tf32r(a0.w);
        da[4*PAD] = tf32r(a1.x); da[5*PAD] = tf32r(a1.y);
        da[6*PAD] = tf32r(a1.z); da[7*PAD] = tf32r(a1.w);
        float* db = &Bs[s][lc][lr];
        db[0*PAD] = tf32r(b0.x); db[1*PAD] = tf32r(b0.y);
        db[2*PAD] = tf32r(b0.z); db[3*PAD] = tf32r(b0.w);
        db[4*PAD] = tf32r(b1.x); db[5*PAD] = tf32r(b1.y);
        db[6*PAD] = tf32r(b1.z); db[7*PAD] = tf32r(b1.w);
    };

    stg(0, pa0, pa1, pb0, pb1);
    __syncthreads();

    const int NC = 64;
    for (int c = 0; c < NC; c++) {
        int s = c & 1;
        if (c + 1 < NC) {
            const float* ap = Ap + (c + 1) * 16;
            const float* bp = Bp + (c + 1) * 16;
            pa0 = *(const float4*)(ap);
            pa1 = *(const float4*)(ap + 4);
            pb0 = *(const float4*)(bp);
            pb1 = *(const float4*)(bp + 4);
        }
        #pragma unroll
        for (int ks = 0; ks < 2; ks++) {
            int kb = ks * 8;
            uint32_t bf[4][2];
            #pragma unroll
            for (int nf = 0; nf < 4; nf++) {
                int col = warp_n * 32 + nf * 8 + r;
                bf[nf][0] = __float_as_uint(Bs[s][kb + cq][col]);
                bf[nf][1] = __float_as_uint(Bs[s][kb + cq + 4][col]);
            }
            #pragma unroll
            for (int mf = 0; mf < 4; mf++) {
                int row0 = warp_m * 64 + mf * 16 + r;
                uint32_t af[4];
                af[0] = __float_as_uint(As[s][kb + cq][row0]);
                af[1] = __float_as_uint(As[s][kb + cq][row0 + 8]);
                af[2] = __float_as_uint(As[s][kb + cq + 4][row0]);
                af[3] = __float_as_uint(As[s][kb + cq + 4][row0 + 8]);
                #pragma unroll
                for (int nf = 0; nf < 4; nf++)
                    mma1688(acc[mf][nf], af, bf[nf]);
            }
        }
        if (c + 1 < NC) {
            stg(s ^ 1, pa0, pa1, pb0, pb1);
            __syncthreads();
        }
    }

    #pragma unroll
    for (int mf = 0; mf < 4; mf++) {
        int row0 = blockIdx.y * 128 + warp_m * 64 + mf * 16 + r;
        #pragma unroll
        for (int nf = 0; nf < 4; nf++) {
            int gcol = blockIdx.x * 128 + warp_n * 32 + nf * 8 + cq * 2;
            float2 bv = *(const float2*)(bias + gcol);
            float2 v0, v1;
            v0.x = acc[mf][nf][0] + bv.x;
            v0.y = acc[mf][nf][1] + bv.y;
            v1.x = acc[mf][nf][2] + bv.x;
            v1.y = acc[mf][nf][3] + bv.y;
            if (MODE == 2) {
                float2 r0 = *(const float2*)(g_xn + (size_t)row0 * 1024 + gcol);
                float2 r1 = *(const float2*)(g_xn + (size_t)(row0 + 8) * 1024 + gcol);
                v0.x += r0.x; v0.y += r0.y;
                v1.x += r1.x; v1.y += r1.y;
            }
            *(float2*)(C + (size_t)row0 * N + gcol)       = v0;
            *(float2*)(C + (size_t)(row0 + 8) * N + gcol) = v1;
        }
    }
}

// ============================================================
// Flash attention on tf32 mma.sync, cp.async double-buffered KV.
// R10-proven core; two changes only:
//   (1) QK^T B-fragments via ldmatrix.x4 (with "memory" clobber)
//   (2) log2-domain softmax (Q pre-scaled by 0.125*log2e; bare ex2)
// CTA = one (b,h) x 128 q rows. 256 threads = 8 warps, warp = 16 q rows.
// KV tiles of 64. K/V raw fp32 (HMMA HW tf32 truncation); Q,P rna-rounded.
// ============================================================
#define PQ  68
#define PK  68
#define PV  72
#define ATTN_SMEM ((128*PQ + 2*64*PK + 2*64*PV) * 4)   // 106496 B
#define QSCALE 0.18033688011112042f   // 0.125 * log2(e)

__global__ __launch_bounds__(256)
void attn_mma(const int* __restrict__ lens)
{
    extern __shared__ float sm[];
    float* Ps = sm;                          // [128][PQ]  Q staging, then P
    float* Ks = sm + 128 * PQ;               // [2][64][PK]  (kv x d)
    float* Vs = sm + 128 * PQ + 2 * 64 * PK; // [2][64][PV]  (kv x d)

    int tid = threadIdx.x;
    int wid = tid >> 5, lane = tid & 31;
    int r = lane >> 2, cq = lane & 3;
    int g = lane >> 3, j = lane & 7;         // ldmatrix address groups
    int b = blockIdx.z, h = blockIdx.y, qb = blockIdx.x * 128;
    int len = lens[b];

    uint32_t ks_u32 = smem_u32(Ks);

    // ldmatrix row/col offset (floats) for K B-frags:
    //   mats: {kv j, d+0}, {kv j, d+4}, {kv 8+j, d+0}, {kv 8+j, d+4}
    uint32_t kRowOff = (uint32_t)((((g >> 1) * 8 + j) * PK) + (g & 1) * 4);

    // cp.async loader: 4 threads per kv row, each thread 64B of K + 64B of V
    int kvr = tid >> 2, loff = (tid & 3) * 16;
    const float* gsrc = g_kv + (size_t)(b * SQL) * 2048 + h * 64;

    uint32_t ks_raw = smem_u32(Ks);
    uint32_t vs_raw = smem_u32(Vs);
    auto issue = [&](int t0, int s) {
        const float* gk = gsrc + (size_t)(t0 + kvr) * 2048 + loff;
        const float* gv = gk + 1024;
        uint32_t dk = ks_raw + (uint32_t)(s * 64 * PK + kvr * PK + loff) * 4u;
        uint32_t dv = vs_raw + (uint32_t)(s * 64 * PV + kvr * PV + loff) * 4u;
        #pragma unroll
        for (int i = 0; i < 4; i++)
            asm volatile("cp.async.ca.shared.global [%0], [%1], 16;"
                         :: "r"(dk + i * 16), "l"(gk + i * 4));
        #pragma unroll
        for (int i = 0; i < 4; i++)
            asm volatile("cp.async.ca.shared.global [%0], [%1], 16;"
                         :: "r"(dv + i * 16), "l"(gv + i * 4));
        asm volatile("cp.async.commit_group;" ::: "memory");
    };

    issue(0, 0);   // prefetch tile 0 while we stage Q

    // ---- stage Q tile (scaled to log2 domain, tf32 rna)
    {
        int row = tid >> 1, dbase = (tid & 1) * 32;
        const float4* src = (const float4*)(g_q + (size_t)(b * SQL + qb + row) * 1024 + h * 64 + dbase);
        float* dst = Ps + row * PQ + dbase;
        #pragma unroll
        for (int i = 0; i < 8; i++) {
            float4 v = src[i];
            dst[i*4+0] = tf32r(v.x * QSCALE);
            dst[i*4+1] = tf32r(v.y * QSCALE);
            dst[i*4+2] = tf32r(v.z * QSCALE);
            dst[i*4+3] = tf32r(v.w * QSCALE);
        }
    }
    __syncthreads();

    int row0 = wid * 16 + r;
    uint32_t qf[8][4];
    #pragma unroll
    for (int kb = 0; kb < 8; kb++) {
        qf[kb][0] = __float_as_uint(Ps[row0 * PQ + kb*8 + cq]);
        qf[kb][1] = __float_as_uint(Ps[(row0 + 8) * PQ + kb*8 + cq]);
        qf[kb][2] = __float_as_uint(Ps[row0 * PQ + kb*8 + cq + 4]);
        qf[kb][3] = __float_as_uint(Ps[(row0 + 8) * PQ + kb*8 + cq + 4]);
    }

    float oacc[8][4];
    #pragma unroll
    for (int i = 0; i < 8; i++) { oacc[i][0]=0.f; oacc[i][1]=0.f; oacc[i][2]=0.f; oacc[i][3]=0.f; }
    float m0 = -1e30f, m1 = -1e30f, l0 = 0.f, l1 = 0.f;

    int q_r  = qb + row0;
    int q_r8 = q_r + 8;
    int qmin = qb + wid * 16;
    int qmax = qmin + 15;

    int kend = min(len, qb + 128);
    int T = (kend + 63) >> 6;

    for (int t = 0; t < T; t++) {
        int s = t & 1;
        int t0 = t * 64;
        if (t + 1 < T) {
            issue((t + 1) * 64, s ^ 1);
            asm volatile("cp.async.wait_group 1;" ::: "memory");
        } else {
            asm volatile("cp.async.wait_group 0;" ::: "memory");
        }
        __syncthreads();   // tile t data visible to all threads

        const float* Vc = Vs + s * 64 * PV;

        if (t0 <= qmax) {   // skip tiles entirely in this warp's causal future
            // ---- S = Q K^T  (B frags via ldmatrix x4: 2 nf per issue)
            uint32_t kbase = ks_u32 + (uint32_t)(s * 64 * PK + kRowOff) * 4u;
            float sacc[8][4];
            #pragma unroll
            for (int i = 0; i < 8; i++) { sacc[i][0]=0.f; sacc[i][1]=0.f; sacc[i][2]=0.f; sacc[i][3]=0.f; }
            #pragma unroll
            for (int kb = 0; kb < 8; kb++) {
                #pragma unroll
                for (int nfp = 0; nfp < 4; nfp++) {
                    uint32_t bf[4];
                    ldm4(bf, kbase + (uint32_t)(nfp * 16 * PK) * 4u + (uint32_t)(kb * 32));
                    mma1688(sacc[2*nfp],     qf[kb], bf);
                    mma1688(sacc[2*nfp + 1], qf[kb], bf + 2);
                }
            }

            // ---- mask (warp-uniform fast path for interior tiles)
            bool nomask = (t0 + 63 <= qmin) && (t0 + 64 <= len);
            if (!nomask) {
                #pragma unroll
                for (int nf = 0; nf < 8; nf++) {
                    int c0 = t0 + nf*8 + 2*cq, c1 = c0 + 1;
                    if (c0 > q_r  || c0 >= len) sacc[nf][0] = -1e30f;
                    if (c1 > q_r  || c1 >= len) sacc[nf][1] = -1e30f;
                    if (c0 > q_r8 || c0 >= len) sacc[nf][2] = -1e30f;
                    if (c1 > q_r8 || c1 >= len) sacc[nf][3] = -1e30f;
                }
            }

            // ---- online softmax (log2 domain; row = quad of 4 lanes)
            float tm0 = -1e30f, tm1 = -1e30f;
            #pragma unroll
            for (int nf = 0; nf < 8; nf++) {
                tm0 = fmaxf(tm0, fmaxf(sacc[nf][0], sacc[nf][1]));
                tm1 = fmaxf(tm1, fmaxf(sacc[nf][2], sacc[nf][3]));
            }
            tm0 = fmaxf(tm0, __shfl_xor_sync(0xffffffffu, tm0, 1));
            tm0 = fmaxf(tm0, __shfl_xor_sync(0xffffffffu, tm0, 2));
            tm1 = fmaxf(tm1, __shfl_xor_sync(0xffffffffu, tm1, 1));
            tm1 = fmaxf(tm1, __shfl_xor_sync(0xffffffffu, tm1, 2));
            float nm0 = fmaxf(m0, tm0), nm1 = fmaxf(m1, tm1);
            float corr0 = ex2f(m0 - nm0), corr1 = ex2f(m1 - nm1);
            m0 = nm0; m1 = nm1;
            l0 *= corr0; l1 *= corr1;
            #pragma unroll
            for (int nf = 0; nf < 8; nf++) {
                oacc[nf][0] *= corr0; oacc[nf][1] *= corr0;
                oacc[nf][2] *= corr1; oacc[nf][3] *= corr1;
            }
            #pragma unroll
            for (int nf = 0; nf < 8; nf++) {
                float p0 = ex2f(sacc[nf][0] - m0);
                float p1 = ex2f(sacc[nf][1] - m0);
                float p2 = ex2f(sacc[nf][2] - m1);
                float p3 = ex2f(sacc[nf][3] - m1);
                l0 += p0 + p1; l1 += p2 + p3;
                float2 lo = make_float2(tf32r(p0), tf32r(p1));
                float2 hi = make_float2(tf32r(p2), tf32r(p3));
                *(float2*)&Ps[row0 * PQ + nf*8 + 2*cq]       = lo;
                *(float2*)&Ps[(row0 + 8) * PQ + nf*8 + 2*cq] = hi;
            }
            __syncwarp();   // Ps rows are warp-private

            // ---- O += P V  (direct-LDS frags, R10-proven)
            #pragma unroll
            for (int kb = 0; kb < 8; kb++) {
                uint32_t af[4];
                af[0] = __float_as_uint(Ps[row0 * PQ + kb*8 + cq]);
                af[1] = __float_as_uint(Ps[(row0 + 8) * PQ + kb*8 + cq]);
                af[2] = __float_as_uint(Ps[row0 * PQ + kb*8 + cq + 4]);
                af[3] = __float_as_uint(Ps[(row0 + 8) * PQ + kb*8 + cq + 4]);
                uint32_t bf[8][2];
                #pragma unroll
                for (int nf = 0; nf < 8; nf++) {
                    bf[nf][0] = __float_as_uint(Vc[(kb*8 + cq) * PV + nf*8 + r]);
                    bf[nf][1] = __float_as_uint(Vc[(kb*8 + cq + 4) * PV + nf*8 + r]);
                }
                #pragma unroll
                for (int nf = 0; nf < 8; nf++)
                    mma1688(oacc[nf], af, bf[nf]);
            }
        }
        __syncthreads();   // all warps done with buf s before it is refilled
    }

    // ---- epilogue
    l0 += __shfl_xor_sync(0xffffffffu, l0, 1);
    l0 += __shfl_xor_sync(0xffffffffu, l0, 2);
    l1 += __shfl_xor_sync(0xffffffffu, l1, 1);
    l1 += __shfl_xor_sync(0xffffffffu, l1, 2);
    float i0 = 1.f / l0, i1 = 1.f / l1;
    float* o0 = g_att + (size_t)(b * SQL + q_r)  * 1024 + h * 64;
    float* o1 = g_att + (size_t)(b * SQL + q_r8) * 1024 + h * 64;
    #pragma unroll
    for (int nf = 0; nf < 8; nf++) {
        *(float2*)&o0[nf*8 + 2*cq] = make_float2(oacc[nf][0] * i0, oacc[nf][1] * i0);
        *(float2*)&o1[nf*8 + 2*cq] = make_float2(oacc[nf][2] * i1, oacc[nf][3] * i1);
    }
}

// ============================================================
// Launch
// ============================================================
extern "C" void kernel_launch(void* const* d_in, const int* in_sizes, int n_in,
                              void* d_out, int out_size)
{
    const float* x    = (const float*)d_in[0];
    // d_in[1] == key_value_sequences, identical to x (self-attention path)
    const int*   lens = (const int*)  d_in[2];
    const float* Wq   = (const float*)d_in[3];
    const float* bq   = (const float*)d_in[4];
    const float* Wkv  = (const float*)d_in[5];
    const float* bkv  = (const float*)d_in[6];
    const float* Wo   = (const float*)d_in[7];
    const float* bo   = (const float*)d_in[8];
    const float* gam  = (const float*)d_in[9];
    const float* bet  = (const float*)d_in[10];
    float* out = (float*)d_out;

    cudaFuncSetAttribute(attn_mma, cudaFuncAttributeMaxDynamicSharedMemorySize, ATTN_SMEM);

    // 1. LayerNorm (shared by q and kv paths)
    ln_kernel<<<ROWS, 256>>>(x, gam, bet);
    // 2. transpose + tf32-round the weights
    transpose_rna<0><<<dim3(32, 32), dim3(32, 8)>>>(Wq, 1024);
    transpose_rna<1><<<dim3(64, 32), dim3(32, 8)>>>(Wkv, 2048);
    transpose_rna<2><<<dim3(32, 32), dim3(32, 8)>>>(Wo, 1024);
    // 3. projections on mma.sync tf32
    mma_gemm<0><<<dim3(8, 64),  256>>>(bq,  nullptr, 1024);
    mma_gemm<1><<<dim3(16, 64), 256>>>(bkv, nullptr, 2048);
    // 4. flash attention on tensor cores (causal + padding), pipelined KV
    attn_mma<<<dim3(8, 16, 8), 256, ATTN_SMEM>>>(lens);
    // 5. out = att @ Wo + bo + residual(xn)
    mma_gemm<2><<<dim3(8, 64),  256>>>(bo, out, 1024);
}